// round 9
// baseline (speedup 1.0000x reference)
#include <cuda_runtime.h>
#include <cuda_bf16.h>
#include <cstdint>

// ---------------------------------------------------------------------------
// Model_70222715289880: bilinear score -> top-k(10/64) -> gather of 10 tensors
// B=8, K=64, TOPK=10, N_R=4, L_R=128, H=512, D=128, D2=640.
//
// R9: q_kernel restructured to kill 8x redundant W traffic — 20 blocks (one
// per 32-e slice) x 8 warps, warp w computes batch b=w. All warps in a block
// share the same W tiles via L2 (13MB -> 1.6MB DRAM). FP chain per (b,e) is
// BIT-IDENTICAL to all passing rounds (serial d 0..639, tiles of 16).
// ---------------------------------------------------------------------------

#define Bq   8
#define Kk   64
#define TOPK 10
#define D2   640

#define OFF_SCORES   0
#define OFF_RATINGS  21238160
#define OFF_IDX      21248480

// vec4 (float4) offsets of gathered segments in dst
#define V4_SR    20u
#define V4_HR    40980u
#define V4_RA    5283860u
#define V4_RO    5294100u
#define V4_MASK  5304340u
#define V4_RB    5304420u
#define V4_RM    5306980u
#define V4_RE    5309560u

// small-gather compacted ranges (f4 units), h_r excluded
#define SM_SR_END  40960u
#define SM_RA_END  51200u
#define SM_RO_END  61440u
#define SM_MK_END  61520u
#define SM_RB_END  64080u
#define SM_RM_END  66640u
#define SM_TOTAL   69200u

#define HR_BLOCKS  5120    // 80 rows * 64 chunks
#define SM_BLOCKS  128

__device__ int   g_topk_idx[Bq * TOPK];
__device__ float g_q[Bq * D2];

// -------------------------------- cp.async --------------------------------
__device__ __forceinline__ void cpa16(uint32_t dst_smem, const void* src) {
    asm volatile("cp.async.cg.shared.global [%0], [%1], 16;"
                 :: "r"(dst_smem), "l"(src));
}
#define CPA_COMMIT()  asm volatile("cp.async.commit_group;")
#define CPA_WAIT(N)   asm volatile("cp.async.wait_group %0;" :: "n"(N) : "memory")

__device__ __forceinline__ uint32_t smem_u32(const void* p) {
    return (uint32_t)__cvta_generic_to_shared(p);
}

// ---------------------------------------------------------------------------
// XLA's tanh (Eigen generic_fast_tanh_float as emitted by elemental_ir_emitter)
// ---------------------------------------------------------------------------
__device__ __forceinline__ float xla_tanhf(float x)
{
    const float kClamp = 7.90531110763549805f;
    float xc = fmaxf(-kClamp, fminf(x, kClamp));
    float x2 = xc * xc;

    float p = fmaf(x2, -2.76076847742355e-16f, 2.00018790482477e-13f);
    p = fmaf(x2, p, -8.60467152213735e-11f);
    p = fmaf(x2, p,  5.12229709037114e-08f);
    p = fmaf(x2, p,  1.48572235717979e-05f);
    p = fmaf(x2, p,  6.37261928875436e-04f);
    p = fmaf(x2, p,  4.89352455891786e-03f);
    p = xc * p;

    float q = fmaf(x2, 1.19825839466702e-06f, 1.18534705686654e-04f);
    q = fmaf(x2, q, 2.26843463243900e-03f);
    q = fmaf(x2, q, 4.89352518554385e-03f);

    float r = p / q;
    return (fabsf(x) < 0.0004f) ? x : r;
}

// total-order key on float (ascending)
__device__ __forceinline__ unsigned ord_f32(float f)
{
    int i = __float_as_int(f);
    return (i < 0) ? ~(unsigned)i : ((unsigned)i | 0x80000000u);
}

// ---------------------------------------------------------------------------
// Kernel Q: q[b][e] = sum_d a_s_q[b][d] * W[d][e]  (serial-d chain per e).
// Grid 20 blocks x 256 threads (8 warps). Block owns e-slice [32*bid, +32);
// warp w computes batch b=w for all 32 e (lane l -> e = 32*bid + l).
// 40 tiles of 16 d; 10-stage warp-private cp.async ring. All 8 warps load
// the SAME W tile addresses -> 1 DRAM miss + 7 L2 hits per line.
// Dynamic smem: 8*640 + 10*8*512 floats = 184,320 B.
// ---------------------------------------------------------------------------
#define QT       16
#define QTILES   40
#define QST      10
#define Q_SMEM   ((8 * D2 + QST * 8 * QT * 32) * 4)

__global__ __launch_bounds__(256) void q_kernel(
    const float* __restrict__ a_s_q,
    const float* __restrict__ W)
{
    extern __shared__ float dynq[];
    float* aq = dynq;                 // [8][640] — all batches
    float* wt = dynq + 8 * D2;        // [QST][8 warps][16*32]

    const int e0  = blockIdx.x * 32;
    const int tid = threadIdx.x;
    const int w   = tid >> 5;
    const int l   = tid & 31;

    for (int i = tid; i < 8 * D2; i += 256) aq[i] = a_s_q[i];
    __syncthreads();   // only block-wide sync; main loop is warp-private

    const int rrow = l >> 3;        // 0..3
    const int c8   = l & 7;         // 0..7
    // per-tile: 4 cp.async per lane; instr i covers rows 4i + rrow
    const float* gsrc0 = W + e0 + c8 * 4 + rrow * D2;
    const uint32_t sbase = smem_u32(wt)
                         + (uint32_t)w * 2048u        // 512 floats / warp
                         + (uint32_t)rrow * 128u
                         + (uint32_t)c8 * 16u;

#define Q_ISSUE(T, ST)                                                        \
    {                                                                         \
        const float* _s = gsrc0 + (T) * QT * D2;                              \
        const uint32_t _d = sbase + (uint32_t)(ST) * 16384u;                  \
        cpa16(_d + 0 * 512, _s + 0 * 4 * D2);                                 \
        cpa16(_d + 1 * 512, _s + 1 * 4 * D2);                                 \
        cpa16(_d + 2 * 512, _s + 2 * 4 * D2);                                 \
        cpa16(_d + 3 * 512, _s + 3 * 4 * D2);                                 \
        CPA_COMMIT();                                                         \
    }

    // prologue: tiles 0..8 into stages 0..8 (9 groups in flight)
    #pragma unroll
    for (int p = 0; p < QST - 1; ++p) Q_ISSUE(p, p)

    const float* aqw = aq + w * D2;   // this warp's batch row
    float s = 0.f;
    int st = 0, nst = QST - 1;
    for (int t = 0; t < QTILES; ++t) {
        CPA_WAIT(QST - 2);
        __syncwarp();
        if (t + QST - 1 < QTILES) { Q_ISSUE(t + QST - 1, nst) } else { CPA_COMMIT(); }
        const float* wrow = wt + st * 4096 + w * 512 + l;
        const int dbase = t * QT;
        #pragma unroll
        for (int i = 0; i < QT; ++i)
            s = fmaf(aqw[dbase + i], wrow[i * 32], s);
        if (++st == QST) st = 0;
        if (++nst == QST) nst = 0;
    }
    g_q[w * D2 + e0 + l] = s;
#undef Q_ISSUE
}

// ---------------------------------------------------------------------------
// Kernel S: scores + top-10 + small outputs. 8 blocks x 256 threads (8 warps).
// Warp w owns k in [8w, 8w+8). 20 tiles of 32 e; 10-stage warp-private ring.
// Dot FP order identical to R2-R8 (4 threads per k, stride-4, shfl 1 then 2).
// Dynamic smem: 640 + 10*8*288 floats = 94,720 B.
// ---------------------------------------------------------------------------
#define SCT      32      // e per tile
#define SROW     36      // padded row stride (floats) -> conflict-free LDS
#define STILES   20
#define SST      10
#define S_SMEM   ((D2 + SST * 8 * 8 * SROW) * 4)

__global__ __launch_bounds__(256) void score_topk_kernel(
    const float* __restrict__ a_s_r,
    const int*   __restrict__ ratings,
    float* __restrict__ out)
{
    __shared__ float sc[Kk];
    extern __shared__ float dyns[];
    float* q_s = dyns;             // [640]
    float* at  = dyns + D2;        // [SST][8][8*SROW]

    const int b   = blockIdx.x;
    const int tid = threadIdx.x;
    const int w   = tid >> 5;
    const int l   = tid & 31;

    for (int i = tid; i < D2; i += 256) q_s[i] = g_q[b * D2 + i];
    __syncthreads();

    const float* abase = a_s_r + (size_t)b * Kk * D2;
    const int rrow = l >> 3;        // 0..3  (covers k_local rrow and rrow+4)
    const int c8   = l & 7;         // 0..7
    const float* gsrc0 = abase + (w * 8 + rrow) * D2 + c8 * 4;
    const uint32_t sbase = smem_u32(at)
                         + (uint32_t)w * (8 * SROW * 4)     // 1152 B / warp
                         + (uint32_t)rrow * (SROW * 4)      // 144 B / row
                         + (uint32_t)c8 * 16;

#define S_ISSUE(T, ST)                                                        \
    {                                                                         \
        const float* _s = gsrc0 + (T) * SCT;                                  \
        const uint32_t _d = sbase + (uint32_t)(ST) * (8 * 8 * SROW * 4);      \
        cpa16(_d,                _s);                                         \
        cpa16(_d + 4 * SROW * 4, _s + 4 * D2);                                \
        CPA_COMMIT();                                                         \
    }

    // prologue: tiles 0..8 into stages 0..8 (9 groups in flight)
    #pragma unroll
    for (int p = 0; p < SST - 1; ++p) S_ISSUE(p, p)

    const int k    = tid >> 2;
    const int sub  = tid & 3;
    const int kloc = k & 7;
    float s = 0.f;
    int st = 0, nst = SST - 1;
    for (int t = 0; t < STILES; ++t) {
        CPA_WAIT(SST - 2);
        __syncwarp();
        if (t + SST - 1 < STILES) { S_ISSUE(t + SST - 1, nst) } else { CPA_COMMIT(); }
        const float* arow = &at[(st * 8 + w) * (8 * SROW) + kloc * SROW + sub];
        const float* qrow = &q_s[SCT * t + sub];
        #pragma unroll
        for (int i = 0; i < 8; ++i)
            s = fmaf(qrow[4 * i], arow[4 * i], s);
        if (++st == SST) st = 0;
        if (++nst == SST) nst = 0;
    }
#undef S_ISSUE

    s += __shfl_xor_sync(0xFFFFFFFFu, s, 1);
    s += __shfl_xor_sync(0xFFFFFFFFu, s, 2);
    if (sub == 0) sc[k] = xla_tanhf(s);
    __syncthreads();

    if (tid < 32) {
        const int lane = tid;
        // key = ord(score) << 7 | (127 - k): max key == max score, min index
        unsigned long long k0 =
            ((unsigned long long)ord_f32(sc[lane]) << 7) | (unsigned)(127 - lane);
        unsigned long long k1 =
            ((unsigned long long)ord_f32(sc[lane + 32]) << 7) | (unsigned)(127 - (lane + 32));

        #pragma unroll
        for (int t = 0; t < TOPK; ++t) {
            unsigned long long m = (k0 > k1) ? k0 : k1;
            #pragma unroll
            for (int o = 16; o > 0; o >>= 1) {
                unsigned long long other = __shfl_xor_sync(0xFFFFFFFFu, m, o);
                if (other > m) m = other;
            }
            const int bk = 127 - (int)(m & 127u);
            if (lane == 0) {
                out[OFF_SCORES  + b * TOPK + t] = sc[bk];
                out[OFF_RATINGS + b * TOPK + t] = (float)ratings[b * Kk + bk];
                out[OFF_IDX     + b * TOPK + t] = (float)bk;
                g_topk_idx[b * TOPK + t] = bk;
            }
            if (bk == lane)      k0 = 0ull;
            if (bk == lane + 32) k1 = 0ull;
        }
    }
}

// ---------------------------------------------------------------------------
// Kernel G: gather. Blocks [0, 5120): branch-free h_r copy (16KB/block,
// 4 independent f4 ld/st per thread, streaming hints). Blocks [5120, 5248):
// grid-stride over the small segments. (Unchanged from R7/R8.)
// ---------------------------------------------------------------------------
__global__ __launch_bounds__(256) void gather_kernel(
    const float4* __restrict__ s_r,
    const float4* __restrict__ h_r,
    const float4* __restrict__ r_a,
    const float4* __restrict__ r_o,
    const float4* __restrict__ mask,
    const int4*   __restrict__ rb,
    const float4* __restrict__ rm,
    const int4*   __restrict__ re,
    float4* __restrict__ out4)
{
    __shared__ int idx_s[Bq * TOPK];
    if (threadIdx.x < Bq * TOPK) idx_s[threadIdx.x] = g_topk_idx[threadIdx.x];
    __syncthreads();

    if (blockIdx.x < HR_BLOCKS) {
        const unsigned row   = blockIdx.x >> 6;          // 0..79
        const unsigned chunk = blockIdx.x & 63u;
        const unsigned b     = row / TOPK;
        const unsigned k     = (unsigned)idx_s[row];
        const float4* src = h_r + (b * Kk + k) * 65536u + chunk * 1024u + threadIdx.x;
        float4*       dst = out4 + V4_HR + row * 65536u + chunk * 1024u + threadIdx.x;
        float4 v0 = __ldcs(src);
        float4 v1 = __ldcs(src + 256);
        float4 v2 = __ldcs(src + 512);
        float4 v3 = __ldcs(src + 768);
        __stcs(dst,       v0);
        __stcs(dst + 256, v1);
        __stcs(dst + 512, v2);
        __stcs(dst + 768, v3);
        return;
    }

    const unsigned stride = SM_BLOCKS * 256u;
    for (unsigned g = (blockIdx.x - HR_BLOCKS) * 256u + threadIdx.x;
         g < SM_TOTAL; g += stride) {
        if (g < SM_SR_END) {
            const unsigned row = g >> 9;
            const unsigned iv  = g & 511u;
            const unsigned b   = row / TOPK;
            const unsigned k   = (unsigned)idx_s[row];
            out4[V4_SR + g] = s_r[(b * Kk + k) * 512u + iv];
        } else if (g < SM_RA_END) {
            const unsigned local = g - SM_SR_END;
            const unsigned row = local >> 7;
            const unsigned iv  = local & 127u;
            const unsigned b   = row / TOPK;
            const unsigned k   = (unsigned)idx_s[row];
            out4[V4_RA + local] = r_a[(b * Kk + k) * 128u + iv];
        } else if (g < SM_RO_END) {
            const unsigned local = g - SM_RA_END;
            const unsigned row = local >> 7;
            const unsigned iv  = local & 127u;
            const unsigned b   = row / TOPK;
            const unsigned k   = (unsigned)idx_s[row];
            out4[V4_RO + local] = r_o[(b * Kk + k) * 128u + iv];
        } else if (g < SM_MK_END) {
            const unsigned local = g - SM_RO_END;   // == row
            const unsigned b = local / TOPK;
            const unsigned k = (unsigned)idx_s[local];
            out4[V4_MASK + local] = mask[b * Kk + k];
        } else if (g < SM_RB_END) {
            const unsigned local = g - SM_MK_END;
            const unsigned row = local >> 5;
            const unsigned iv  = local & 31u;
            const unsigned b   = row / TOPK;
            const unsigned k   = (unsigned)idx_s[row];
            const int4 v = rb[(b * Kk + k) * 32u + iv];
            out4[V4_RB + local] = make_float4((float)v.x, (float)v.y, (float)v.z, (float)v.w);
        } else if (g < SM_RM_END) {
            const unsigned local = g - SM_RB_END;
            const unsigned row = local >> 5;
            const unsigned iv  = local & 31u;
            const unsigned b   = row / TOPK;
            const unsigned k   = (unsigned)idx_s[row];
            out4[V4_RM + local] = rm[(b * Kk + k) * 32u + iv];
        } else {
            const unsigned local = g - SM_RM_END;
            const unsigned row = local >> 5;
            const unsigned iv  = local & 31u;
            const unsigned b   = row / TOPK;
            const unsigned k   = (unsigned)idx_s[row];
            const int4 v = re[(b * Kk + k) * 32u + iv];
            out4[V4_RE + local] = make_float4((float)v.x, (float)v.y, (float)v.z, (float)v.w);
        }
    }
}

// ---------------------------------------------------------------------------
extern "C" void kernel_launch(void* const* d_in, const int* in_sizes, int n_in,
                              void* d_out, int out_size)
{
    const float* a_s_q   = (const float*)d_in[0];
    const float* a_s_r   = (const float*)d_in[1];
    const float* W       = (const float*)d_in[2];
    const float* s_r     = (const float*)d_in[3];
    const float* h_r     = (const float*)d_in[4];
    const float* r_a     = (const float*)d_in[5];
    const float* r_o     = (const float*)d_in[6];
    const float* mask    = (const float*)d_in[7];
    const int*   rb      = (const int*)d_in[8];
    const float* rm      = (const float*)d_in[9];
    const int*   ratings = (const int*)d_in[10];
    const int*   re      = (const int*)d_in[11];
    float* out = (float*)d_out;

    // opt-in to >48KB dynamic smem (host-side attribute; idempotent,
    // executes at capture time, no device allocation)
    static int attr_done = 0;
    if (!attr_done) {
        cudaFuncSetAttribute(q_kernel,
            cudaFuncAttributeMaxDynamicSharedMemorySize, Q_SMEM);
        cudaFuncSetAttribute(score_topk_kernel,
            cudaFuncAttributeMaxDynamicSharedMemorySize, S_SMEM);
        attr_done = 1;
    }

    q_kernel<<<20, 256, Q_SMEM>>>(a_s_q, W);
    score_topk_kernel<<<Bq, 256, S_SMEM>>>(a_s_r, ratings, out);
    gather_kernel<<<HR_BLOCKS + SM_BLOCKS, 256>>>(
        (const float4*)s_r, (const float4*)h_r, (const float4*)r_a,
        (const float4*)r_o, (const float4*)mask, (const int4*)rb,
        (const float4*)rm, (const int4*)re, (float4*)out);
}

// round 10
// speedup vs baseline: 1.1133x; 1.1133x over previous
#include <cuda_runtime.h>
#include <cuda_bf16.h>
#include <cstdint>

// ---------------------------------------------------------------------------
// Model_70222715289880: bilinear score -> top-k(10/64) -> gather of 10 tensors
// B=8, K=64, TOPK=10, N_R=4, L_R=128, H=512, D=128, D2=640.
//
// R10: kill the staged pipelines entirely. Per-block working sets are ~100KB
// (< 228KB smem), so: ONE cp.async burst loads everything, ONE wait, then the
// serial fmaf chains run uninterrupted from smem. 40 tile-waits -> 1.
// FP summation order is BIT-IDENTICAL to all passing rounds (R2-R9).
// ---------------------------------------------------------------------------

#define Bq   8
#define Kk   64
#define TOPK 10
#define D2   640

#define OFF_SCORES   0
#define OFF_RATINGS  21238160
#define OFF_IDX      21248480

// vec4 (float4) offsets of gathered segments in dst
#define V4_SR    20u
#define V4_HR    40980u
#define V4_RA    5283860u
#define V4_RO    5294100u
#define V4_MASK  5304340u
#define V4_RB    5304420u
#define V4_RM    5306980u
#define V4_RE    5309560u

// small-gather compacted ranges (f4 units), h_r excluded
#define SM_SR_END  40960u
#define SM_RA_END  51200u
#define SM_RO_END  61440u
#define SM_MK_END  61520u
#define SM_RB_END  64080u
#define SM_RM_END  66640u
#define SM_TOTAL   69200u

#define HR_BLOCKS  5120    // 80 rows * 64 chunks
#define SM_BLOCKS  128

__device__ int   g_topk_idx[Bq * TOPK];
__device__ float g_q[Bq * D2];

// -------------------------------- cp.async --------------------------------
__device__ __forceinline__ void cpa16(uint32_t dst_smem, const void* src) {
    asm volatile("cp.async.cg.shared.global [%0], [%1], 16;"
                 :: "r"(dst_smem), "l"(src));
}
#define CPA_COMMIT()  asm volatile("cp.async.commit_group;")
#define CPA_WAIT0()   asm volatile("cp.async.wait_group 0;" ::: "memory")

__device__ __forceinline__ uint32_t smem_u32(const void* p) {
    return (uint32_t)__cvta_generic_to_shared(p);
}

// ---------------------------------------------------------------------------
// XLA's tanh (Eigen generic_fast_tanh_float as emitted by elemental_ir_emitter)
// ---------------------------------------------------------------------------
__device__ __forceinline__ float xla_tanhf(float x)
{
    const float kClamp = 7.90531110763549805f;
    float xc = fmaxf(-kClamp, fminf(x, kClamp));
    float x2 = xc * xc;

    float p = fmaf(x2, -2.76076847742355e-16f, 2.00018790482477e-13f);
    p = fmaf(x2, p, -8.60467152213735e-11f);
    p = fmaf(x2, p,  5.12229709037114e-08f);
    p = fmaf(x2, p,  1.48572235717979e-05f);
    p = fmaf(x2, p,  6.37261928875436e-04f);
    p = fmaf(x2, p,  4.89352455891786e-03f);
    p = xc * p;

    float q = fmaf(x2, 1.19825839466702e-06f, 1.18534705686654e-04f);
    q = fmaf(x2, q, 2.26843463243900e-03f);
    q = fmaf(x2, q, 4.89352518554385e-03f);

    float r = p / q;
    return (fabsf(x) < 0.0004f) ? x : r;
}

// total-order key on float (ascending)
__device__ __forceinline__ unsigned ord_f32(float f)
{
    int i = __float_as_int(f);
    return (i < 0) ? ~(unsigned)i : ((unsigned)i | 0x80000000u);
}

// ---------------------------------------------------------------------------
// Kernel Q: q[b][e] = sum_d a_s_q[b][d] * W[d][e]  (serial-d chain, d asc).
// 40 blocks x 128 threads (4 warps). Block (es, bg) = (bid%20, bid/20):
// e-slice [32*es, +32), batches [4*bg, +4). Warp w -> b = 4*bg + w,
// lane l -> e = 32*es + l.
// ONE cp.async burst: a_s_q (all 8 rows, 20KB) + W slice (640x32, 80KB).
// Dynamic smem: 102,400 B.
// ---------------------------------------------------------------------------
#define Q_SMEM  ((8 * D2 + D2 * 32) * 4)

__global__ __launch_bounds__(128) void q_kernel(
    const float* __restrict__ a_s_q,
    const float* __restrict__ W)
{
    extern __shared__ float dynq[];
    float* aq = dynq;                 // [8][640]
    float* wt = dynq + 8 * D2;        // [640][32]  row stride 32 floats

    const int tid = threadIdx.x;
    const int w   = tid >> 5;
    const int l   = tid & 31;
    const int es  = blockIdx.x % 20;
    const int bg  = blockIdx.x / 20;
    const int e0  = es * 32;

    // a_s_q: 5120 floats = 1280 f4 -> 10 per thread
    const uint32_t aq_s = smem_u32(aq);
    #pragma unroll
    for (int r = 0; r < 10; ++r) {
        const int j = tid + 128 * r;
        cpa16(aq_s + (uint32_t)j * 16u, a_s_q + j * 4);
    }
    // W slice: 640 rows x 8 f4 = 5120 f4 -> 40 per thread
    // j = tid + 128*r: row = j>>3, c = j&7; smem off = j*16 B (row*128 + c*16)
    const uint32_t wt_s = smem_u32(wt);
    #pragma unroll
    for (int r = 0; r < 40; ++r) {
        const int j   = tid + 128 * r;
        const int row = j >> 3;
        const int c   = j & 7;
        cpa16(wt_s + (uint32_t)j * 16u, W + row * D2 + e0 + c * 4);
    }
    CPA_COMMIT();
    CPA_WAIT0();
    __syncthreads();

    const int b = bg * 4 + w;
    const float* aqb = aq + b * D2;
    const float* wl  = wt + l;
    float s = 0.f;
    #pragma unroll 16
    for (int d = 0; d < D2; ++d)
        s = fmaf(aqb[d], wl[d * 32], s);
    g_q[b * D2 + e0 + l] = s;
}

// ---------------------------------------------------------------------------
// Kernel S: scores + top-10 + small outputs. 8 blocks x 256 threads.
// ONE cp.async burst loads the whole a_s_r[b] block (64 x 640, rows padded
// to 652 floats -> conflict-free LDS) + q row. Then the R2-identical dot
// (4 threads per k, stride-4 chains, shfl 1 then 2) and warp top-k.
// Dynamic smem: 640 + 64*652 floats = 169,472 B.
// ---------------------------------------------------------------------------
#define SROW2   652
#define S_SMEM  ((D2 + Kk * SROW2) * 4)

__global__ __launch_bounds__(256) void score_topk_kernel(
    const float* __restrict__ a_s_r,
    const int*   __restrict__ ratings,
    float* __restrict__ out)
{
    __shared__ float sc[Kk];
    extern __shared__ float dyns[];
    float* q_s = dyns;             // [640]
    float* at  = dyns + D2;        // [64][652]

    const int b   = blockIdx.x;
    const int tid = threadIdx.x;

    // q row: 160 f4
    const uint32_t q_ss = smem_u32(q_s);
    if (tid < 160) cpa16(q_ss + (uint32_t)tid * 16u, g_q + b * D2 + tid * 4);

    // a_s_r block: 64 rows x 160 f4 = 10240 f4 -> 40 per thread
    const float* abase = a_s_r + (size_t)b * Kk * D2;
    const uint32_t at_s = smem_u32(at);
    #pragma unroll
    for (int r = 0; r < 40; ++r) {
        const int j   = tid + 256 * r;
        const int row = j / 160;
        const int col = j % 160;
        cpa16(at_s + (uint32_t)(row * SROW2 * 4 + col * 16),
              abase + row * D2 + col * 4);
    }
    CPA_COMMIT();
    CPA_WAIT0();
    __syncthreads();

    const int k   = tid >> 2;
    const int sub = tid & 3;
    {
        const float* arow = at + k * SROW2 + sub;
        const float* qrow = q_s + sub;
        float s = 0.f;
        #pragma unroll 16
        for (int i = 0; i < 160; ++i)
            s = fmaf(qrow[4 * i], arow[4 * i], s);
        s += __shfl_xor_sync(0xFFFFFFFFu, s, 1);
        s += __shfl_xor_sync(0xFFFFFFFFu, s, 2);
        if (sub == 0) sc[k] = xla_tanhf(s);
    }
    __syncthreads();

    if (tid < 32) {
        const int lane = tid;
        // key = ord(score) << 7 | (127 - k): max key == max score, min index
        unsigned long long k0 =
            ((unsigned long long)ord_f32(sc[lane]) << 7) | (unsigned)(127 - lane);
        unsigned long long k1 =
            ((unsigned long long)ord_f32(sc[lane + 32]) << 7) | (unsigned)(127 - (lane + 32));

        #pragma unroll
        for (int t = 0; t < TOPK; ++t) {
            unsigned long long m = (k0 > k1) ? k0 : k1;
            #pragma unroll
            for (int o = 16; o > 0; o >>= 1) {
                unsigned long long other = __shfl_xor_sync(0xFFFFFFFFu, m, o);
                if (other > m) m = other;
            }
            const int bk = 127 - (int)(m & 127u);
            if (lane == 0) {
                out[OFF_SCORES  + b * TOPK + t] = sc[bk];
                out[OFF_RATINGS + b * TOPK + t] = (float)ratings[b * Kk + bk];
                out[OFF_IDX     + b * TOPK + t] = (float)bk;
                g_topk_idx[b * TOPK + t] = bk;
            }
            if (bk == lane)      k0 = 0ull;
            if (bk == lane + 32) k1 = 0ull;
        }
    }
}

// ---------------------------------------------------------------------------
// Kernel G: gather. Blocks [0, 5120): branch-free h_r copy (16KB/block,
// 4 independent f4 ld/st per thread, streaming hints). Blocks [5120, 5248):
// grid-stride over the small segments. (Unchanged from R7/R8.)
// ---------------------------------------------------------------------------
__global__ __launch_bounds__(256) void gather_kernel(
    const float4* __restrict__ s_r,
    const float4* __restrict__ h_r,
    const float4* __restrict__ r_a,
    const float4* __restrict__ r_o,
    const float4* __restrict__ mask,
    const int4*   __restrict__ rb,
    const float4* __restrict__ rm,
    const int4*   __restrict__ re,
    float4* __restrict__ out4)
{
    __shared__ int idx_s[Bq * TOPK];
    if (threadIdx.x < Bq * TOPK) idx_s[threadIdx.x] = g_topk_idx[threadIdx.x];
    __syncthreads();

    if (blockIdx.x < HR_BLOCKS) {
        const unsigned row   = blockIdx.x >> 6;          // 0..79
        const unsigned chunk = blockIdx.x & 63u;
        const unsigned b     = row / TOPK;
        const unsigned k     = (unsigned)idx_s[row];
        const float4* src = h_r + (b * Kk + k) * 65536u + chunk * 1024u + threadIdx.x;
        float4*       dst = out4 + V4_HR + row * 65536u + chunk * 1024u + threadIdx.x;
        float4 v0 = __ldcs(src);
        float4 v1 = __ldcs(src + 256);
        float4 v2 = __ldcs(src + 512);
        float4 v3 = __ldcs(src + 768);
        __stcs(dst,       v0);
        __stcs(dst + 256, v1);
        __stcs(dst + 512, v2);
        __stcs(dst + 768, v3);
        return;
    }

    const unsigned stride = SM_BLOCKS * 256u;
    for (unsigned g = (blockIdx.x - HR_BLOCKS) * 256u + threadIdx.x;
         g < SM_TOTAL; g += stride) {
        if (g < SM_SR_END) {
            const unsigned row = g >> 9;
            const unsigned iv  = g & 511u;
            const unsigned b   = row / TOPK;
            const unsigned k   = (unsigned)idx_s[row];
            out4[V4_SR + g] = s_r[(b * Kk + k) * 512u + iv];
        } else if (g < SM_RA_END) {
            const unsigned local = g - SM_SR_END;
            const unsigned row = local >> 7;
            const unsigned iv  = local & 127u;
            const unsigned b   = row / TOPK;
            const unsigned k   = (unsigned)idx_s[row];
            out4[V4_RA + local] = r_a[(b * Kk + k) * 128u + iv];
        } else if (g < SM_RO_END) {
            const unsigned local = g - SM_RA_END;
            const unsigned row = local >> 7;
            const unsigned iv  = local & 127u;
            const unsigned b   = row / TOPK;
            const unsigned k   = (unsigned)idx_s[row];
            out4[V4_RO + local] = r_o[(b * Kk + k) * 128u + iv];
        } else if (g < SM_MK_END) {
            const unsigned local = g - SM_RO_END;   // == row
            const unsigned b = local / TOPK;
            const unsigned k = (unsigned)idx_s[local];
            out4[V4_MASK + local] = mask[b * Kk + k];
        } else if (g < SM_RB_END) {
            const unsigned local = g - SM_MK_END;
            const unsigned row = local >> 5;
            const unsigned iv  = local & 31u;
            const unsigned b   = row / TOPK;
            const unsigned k   = (unsigned)idx_s[row];
            const int4 v = rb[(b * Kk + k) * 32u + iv];
            out4[V4_RB + local] = make_float4((float)v.x, (float)v.y, (float)v.z, (float)v.w);
        } else if (g < SM_RM_END) {
            const unsigned local = g - SM_RB_END;
            const unsigned row = local >> 5;
            const unsigned iv  = local & 31u;
            const unsigned b   = row / TOPK;
            const unsigned k   = (unsigned)idx_s[row];
            out4[V4_RM + local] = rm[(b * Kk + k) * 32u + iv];
        } else {
            const unsigned local = g - SM_RM_END;
            const unsigned row = local >> 5;
            const unsigned iv  = local & 31u;
            const unsigned b   = row / TOPK;
            const unsigned k   = (unsigned)idx_s[row];
            const int4 v = re[(b * Kk + k) * 32u + iv];
            out4[V4_RE + local] = make_float4((float)v.x, (float)v.y, (float)v.z, (float)v.w);
        }
    }
}

// ---------------------------------------------------------------------------
extern "C" void kernel_launch(void* const* d_in, const int* in_sizes, int n_in,
                              void* d_out, int out_size)
{
    const float* a_s_q   = (const float*)d_in[0];
    const float* a_s_r   = (const float*)d_in[1];
    const float* W       = (const float*)d_in[2];
    const float* s_r     = (const float*)d_in[3];
    const float* h_r     = (const float*)d_in[4];
    const float* r_a     = (const float*)d_in[5];
    const float* r_o     = (const float*)d_in[6];
    const float* mask    = (const float*)d_in[7];
    const int*   rb      = (const int*)d_in[8];
    const float* rm      = (const float*)d_in[9];
    const int*   ratings = (const int*)d_in[10];
    const int*   re      = (const int*)d_in[11];
    float* out = (float*)d_out;

    // opt-in to >48KB dynamic smem (host-side attribute; idempotent,
    // executes at capture time, no device allocation)
    static int attr_done = 0;
    if (!attr_done) {
        cudaFuncSetAttribute(q_kernel,
            cudaFuncAttributeMaxDynamicSharedMemorySize, Q_SMEM);
        cudaFuncSetAttribute(score_topk_kernel,
            cudaFuncAttributeMaxDynamicSharedMemorySize, S_SMEM);
        attr_done = 1;
    }

    q_kernel<<<40, 128, Q_SMEM>>>(a_s_q, W);
    score_topk_kernel<<<Bq, 256, S_SMEM>>>(a_s_r, ratings, out);
    gather_kernel<<<HR_BLOCKS + SM_BLOCKS, 256>>>(
        (const float4*)s_r, (const float4*)h_r, (const float4*)r_a,
        (const float4*)r_o, (const float4*)mask, (const int4*)rb,
        (const float4*)rm, (const int4*)re, (float4*)out);
}